// round 5
// baseline (speedup 1.0000x reference)
#include <cuda_runtime.h>
#include <math.h>
#include <stdint.h>

#define Bdim 2
#define Ndim 2048
#define Edim 384
#define DPdim 16
#define KSEL 32
#define EPSV 1e-8f
#define TN 64
#define NT (Ndim / TN)            // 32
#define NTRI (NT * (NT + 1) / 2)  // 528

// scratch (device globals: no allocation allowed)
__device__ float g_z[Bdim * Ndim * DPdim];
__device__ float g_rz[Bdim * Ndim];
__device__ float g_rp[Ndim];
__device__ float g_A[(size_t)Bdim * Ndim * Ndim];  // 33.5 MB dense prior matrix

// ---------------- packed f32x2 helpers (Blackwell double-rate FP32) ---------
__device__ __forceinline__ uint64_t pack2(float lo, float hi) {
    uint64_t r; asm("mov.b64 %0, {%1, %2};" : "=l"(r) : "f"(lo), "f"(hi)); return r;
}
__device__ __forceinline__ void unpack2(uint64_t v, float& lo, float& hi) {
    asm("mov.b64 {%0, %1}, %2;" : "=f"(lo), "=f"(hi) : "l"(v));
}
__device__ __forceinline__ uint64_t fma2(uint64_t a, uint64_t b, uint64_t c) {
    uint64_t d; asm("fma.rn.f32x2 %0, %1, %2, %3;" : "=l"(d) : "l"(a), "l"(b), "l"(c)); return d;
}
__device__ __forceinline__ uint64_t mul2(uint64_t a, uint64_t b) {
    uint64_t d; asm("mul.rn.f32x2 %0, %1, %2;" : "=l"(d) : "l"(a), "l"(b)); return d;
}
__device__ __forceinline__ uint64_t add2(uint64_t a, uint64_t b) {
    uint64_t d; asm("add.rn.f32x2 %0, %1, %2;" : "=l"(d) : "l"(a), "l"(b)); return d;
}

// packed exact-gelu via A&S 7.1.26 erf (5-term, |err| <= 1.5e-7), 2 at once.
// poly constants pre-negated so r = fma(-poly, q, 1) = 1 - poly*exp(-x^2).
__device__ __forceinline__ uint64_t gelu2(uint64_t x2) {
    const uint64_t INVS2_2 = pack2(0.70710678118654752f, 0.70710678118654752f);
    const uint64_t ONE2 = pack2(1.0f, 1.0f);
    const uint64_t HALF2 = pack2(0.5f, 0.5f);
    const uint64_t C0_2 = pack2(0.3275911f, 0.3275911f);
    const uint64_t A1_2 = pack2(-0.254829592f, -0.254829592f);
    const uint64_t A2_2 = pack2(0.284496736f, 0.284496736f);
    const uint64_t A3_2 = pack2(-1.421413741f, -1.421413741f);
    const uint64_t A4_2 = pack2(1.453152027f, 1.453152027f);
    const uint64_t A5_2 = pack2(-1.061405429f, -1.061405429f);
    const uint64_t NL2E_2 = pack2(-1.4426950408889634f, -1.4426950408889634f);

    uint64_t y2 = mul2(x2, INVS2_2);
    uint64_t ax2; asm("and.b64 %0, %1, 0x7FFFFFFF7FFFFFFF;" : "=l"(ax2) : "l"(y2));
    uint64_t den2 = fma2(ax2, C0_2, ONE2);
    float dl, dh; unpack2(den2, dl, dh);
    float rl, rh;
    asm("rcp.approx.f32 %0, %1;" : "=f"(rl) : "f"(dl));
    asm("rcp.approx.f32 %0, %1;" : "=f"(rh) : "f"(dh));
    uint64_t t2 = pack2(rl, rh);
    uint64_t p2 = fma2(t2, A5_2, A4_2);
    p2 = fma2(t2, p2, A3_2);
    p2 = fma2(t2, p2, A2_2);
    p2 = fma2(t2, p2, A1_2);
    p2 = mul2(t2, p2);                       // -poly(t)
    uint64_t m2 = mul2(ax2, ax2);
    uint64_t n2 = mul2(m2, NL2E_2);
    float nl, nh; unpack2(n2, nl, nh);
    float ql, qh;
    asm("ex2.approx.f32 %0, %1;" : "=f"(ql) : "f"(nl));
    asm("ex2.approx.f32 %0, %1;" : "=f"(qh) : "f"(nh));
    uint64_t q2 = pack2(ql, qh);
    uint64_t r2 = fma2(p2, q2, ONE2);        // 1 - poly*exp >= 0
    uint64_t sg2; asm("and.b64 %0, %1, 0x8000000080000000;" : "=l"(sg2) : "l"(y2));
    uint64_t erf2; asm("or.b64 %0, %1, %2;" : "=l"(erf2) : "l"(r2), "l"(sg2));
    uint64_t u2 = add2(erf2, ONE2);
    uint64_t xh2 = mul2(x2, HALF2);
    return mul2(xh2, u2);
}

// scalar exact-gelu (z_kernel only; A&S 7.1.26)
__device__ __forceinline__ float erf_fast(float x) {
    float ax = fabsf(x);
    float t = __fdividef(1.0f, fmaf(0.3275911f, ax, 1.0f));
    float poly = t * fmaf(t, fmaf(t, fmaf(t, fmaf(t, 1.061405429f, -1.453152027f),
                                          1.421413741f), -0.284496736f), 0.254829592f);
    float r = 1.0f - poly * __expf(-ax * ax);
    return copysignf(r, x);
}
__device__ __forceinline__ float gelu_exact(float x) {
    return 0.5f * x * (1.0f + erf_fast(x * 0.70710678118654752f));
}

// ---------------- kernel 1: rp[n] = ||positions[n]||^2 ----------------
__global__ void prep_kernel(const float* __restrict__ positions) {
    int n = blockIdx.x * blockDim.x + threadIdx.x;
    if (n < Ndim) {
        float x = positions[3 * n + 0];
        float y = positions[3 * n + 1];
        float z = positions[3 * n + 2];
        g_rp[n] = x * x + y * y + z * z;
    }
}

// ---------------- kernel 2: z = gelu(f@Wi1+bi1)@Wi2+bi2, rz = ||z||^2 ----
__global__ __launch_bounds__(256) void z_kernel(
    const float* __restrict__ feat, const float* __restrict__ Wi1,
    const float* __restrict__ bi1, const float* __restrict__ Wi2,
    const float* __restrict__ bi2)
{
    int gwarp = (blockIdx.x * blockDim.x + threadIdx.x) >> 5;
    int lane = threadIdx.x & 31;
    if (gwarp >= Bdim * Ndim) return;

    const float* x = feat + (size_t)gwarp * Edim;
    float acc = 0.0f;
    for (int e0 = 0; e0 < Edim; e0 += 32) {
        float xv = x[e0 + lane];
#pragma unroll
        for (int i = 0; i < 32; i++) {
            float xb = __shfl_sync(0xffffffffu, xv, i);
            acc = fmaf(xb, Wi1[(e0 + i) * 32 + lane], acc);
        }
    }
    float hg = gelu_exact(acc + bi1[lane]);

    float wv[DPdim];
#pragma unroll
    for (int d = 0; d < DPdim; d++) wv[d] = Wi2[lane * DPdim + d];

    float zv = 0.0f;
#pragma unroll
    for (int d = 0; d < DPdim; d++) {
        float p = hg * wv[d];
#pragma unroll
        for (int off = 16; off > 0; off >>= 1)
            p += __shfl_xor_sync(0xffffffffu, p, off);
        if (lane == d) zv = p + bi2[d];
    }
    if (lane < DPdim) g_z[gwarp * DPdim + lane] = zv;

    float q = (lane < DPdim) ? zv * zv : 0.0f;
#pragma unroll
    for (int off = 16; off > 0; off >>= 1)
        q += __shfl_xor_sync(0xffffffffu, q, off);
    if (lane == 0) g_rz[gwarp] = q;
}

// ---------------- kernel 3: triangular tile pair-compute -> g_A -------------
// 64x64 tile per block (ti <= tj), both orientations written (A is symmetric
// by construction). Fixed column j per thread, 2 i-rows per iteration.
// Boundary-MLP matmul + gelu + Wb2 dot all run on packed f32x2 (FFMA2).
__global__ __launch_bounds__(256, 2) void tile_kernel(
    const float* __restrict__ positions,
    const float* __restrict__ Wb1, const float* __restrict__ bb1,
    const float* __restrict__ Wb2, const float* __restrict__ bb2,
    const float* __restrict__ p_sig, const float* __restrict__ p_tau,
    const float* __restrict__ p_alp, const float* __restrict__ prior_logits)
{
    __shared__ float sZi[TN * DPdim];
    __shared__ float sRzI[TN], sRpI[TN];
    __shared__ float sPiX[TN], sPiY[TN], sPiZ[TN];
    __shared__ ulonglong2 sWb1u[64];   // Wb1 rows as packed f32x2 pairs
    __shared__ uint64_t sWb2u[8];
    __shared__ uint64_t sBb1u[8];
    __shared__ float sScal[8]; // inv2sig, inv2tau, alpha, w0..w3, bb2
    __shared__ float sTile[TN][TN + 1];

    const int tid = threadIdx.x;
    const int jl = tid & 63;
    const int ig = tid >> 6;   // 0..3: i-band of 16 rows

    // decode (b, ti, tj)
    int blk = blockIdx.x;
    const int b = blk / NTRI;
    int tri = blk - b * NTRI;
    int ti = 0;
    while (tri >= NT - ti) { tri -= NT - ti; ti++; }
    const int tj = ti + tri;
    const int I = ti * TN, J = tj * TN;

    // cooperative loads
    if (tid < 64) sWb1u[tid] = ((const ulonglong2*)Wb1)[tid];
    if (tid >= 64 && tid < 72) {
        sWb2u[tid - 64] = ((const uint64_t*)Wb2)[tid - 64];
        sBb1u[tid - 64] = ((const uint64_t*)bb1)[tid - 64];
    }
    {   // sZi: 64 rows x 16 floats = 256 float4
        const float4* zgi = (const float4*)(g_z + ((size_t)b * Ndim + I) * DPdim);
        ((float4*)sZi)[tid] = zgi[tid];
    }
    if (tid < 64) {
        int gi = I + tid;
        sRzI[tid] = g_rz[(size_t)b * Ndim + gi];
        sRpI[tid] = g_rp[gi];
        sPiX[tid] = positions[3 * gi + 0];
        sPiY[tid] = positions[3 * gi + 1];
        sPiZ[tid] = positions[3 * gi + 2];
    }
    if (tid == 128) {
        float sg = log1pf(__expf(p_sig[0]));
        float ta = log1pf(__expf(p_tau[0]));
        float al = log1pf(__expf(p_alp[0]));
        sScal[0] = __fdividef(1.0f, 2.0f * sg * sg + EPSV);
        sScal[1] = __fdividef(1.0f, 2.0f * ta * ta + EPSV);
        sScal[2] = al;
        float l0 = prior_logits[0], l1 = prior_logits[1];
        float l2 = prior_logits[2], l3 = prior_logits[3];
        float m = fmaxf(fmaxf(l0, l1), fmaxf(l2, l3));
        float e0 = __expf(l0 - m), e1 = __expf(l1 - m);
        float e2 = __expf(l2 - m), e3 = __expf(l3 - m);
        float inv = __fdividef(1.0f, e0 + e1 + e2 + e3);
        sScal[3] = e0 * inv; sScal[4] = e1 * inv;
        sScal[5] = e2 * inv; sScal[6] = e3 * inv;
        sScal[7] = bb2[0];
    }

    // per-thread j-side data (fixed column)
    const int gj = J + jl;
    float zjf[DPdim];
    {
        const float4* zgj = (const float4*)(g_z + ((size_t)b * Ndim + gj) * DPdim);
        float4* v = (float4*)zjf;
#pragma unroll
        for (int q = 0; q < 4; q++) v[q] = zgj[q];
    }
    const float rzj = g_rz[(size_t)b * Ndim + gj];
    const float rpj = g_rp[gj];
    const float pjx = positions[3 * gj + 0];
    const float pjy = positions[3 * gj + 1];
    const float pjz = positions[3 * gj + 2];

    __syncthreads();

    const float inv2sig = sScal[0], inv2tau = sScal[1], alpha = sScal[2];
    const float w0 = sScal[3], w1 = sScal[4], w2 = sScal[5], w3 = sScal[6];
    const float bb2v = sScal[7];

    // 8 iterations x 2 i-rows per thread
#pragma unroll 1
    for (int it = 0; it < 8; it++) {
        const int i0 = ig * 16 + it * 2;
        const int i1 = i0 + 1;

        uint64_t h0[8], h1[8];
#pragma unroll
        for (int q = 0; q < 8; q++) { h0[q] = sBb1u[q]; h1[q] = sBb1u[q]; }

        float dz0 = 0.0f, dz1 = 0.0f;
#pragma unroll
        for (int d = 0; d < DPdim; d++) {
            float zjd = zjf[d];
            float zi0 = sZi[i0 * DPdim + d];
            float zi1 = sZi[i1 * DPdim + d];
            dz0 = fmaf(zi0, zjd, dz0);
            dz1 = fmaf(zi1, zjd, dz1);
            float e0 = fabsf(zi0 - zjd);
            float e1 = fabsf(zi1 - zjd);
            uint64_t e0p = pack2(e0, e0);
            uint64_t e1p = pack2(e1, e1);
            ulonglong2 wA = sWb1u[d * 4 + 0];
            ulonglong2 wB = sWb1u[d * 4 + 1];
            ulonglong2 wC = sWb1u[d * 4 + 2];
            ulonglong2 wD = sWb1u[d * 4 + 3];
            h0[0] = fma2(e0p, wA.x, h0[0]);  h0[1] = fma2(e0p, wA.y, h0[1]);
            h0[2] = fma2(e0p, wB.x, h0[2]);  h0[3] = fma2(e0p, wB.y, h0[3]);
            h0[4] = fma2(e0p, wC.x, h0[4]);  h0[5] = fma2(e0p, wC.y, h0[5]);
            h0[6] = fma2(e0p, wD.x, h0[6]);  h0[7] = fma2(e0p, wD.y, h0[7]);
            h1[0] = fma2(e1p, wA.x, h1[0]);  h1[1] = fma2(e1p, wA.y, h1[1]);
            h1[2] = fma2(e1p, wB.x, h1[2]);  h1[3] = fma2(e1p, wB.y, h1[3]);
            h1[4] = fma2(e1p, wC.x, h1[4]);  h1[5] = fma2(e1p, wC.y, h1[5]);
            h1[6] = fma2(e1p, wD.x, h1[6]);  h1[7] = fma2(e1p, wD.y, h1[7]);
        }

        // boundary score: s = bb2 + sum_o gelu(h[o]) * Wb2[o]  (packed)
        uint64_t s0p = pack2(bb2v, 0.0f);
        uint64_t s1p = pack2(bb2v, 0.0f);
#pragma unroll
        for (int q = 0; q < 8; q++) {
            uint64_t wb = sWb2u[q];
            s0p = fma2(gelu2(h0[q]), wb, s0p);
            s1p = fma2(gelu2(h1[q]), wb, s1p);
        }
        float s0a, s0b, s1a, s1b;
        unpack2(s0p, s0a, s0b);
        unpack2(s1p, s1a, s1b);
        float s0 = s0a + s0b, s1 = s1a + s1b;

        float abnd0 = __fdividef(1.0f, 1.0f + __expf(alpha * s0));
        float abnd1 = __fdividef(1.0f, 1.0f + __expf(alpha * s1));

        float d2z0 = fmaxf(sRzI[i0] + rzj - 2.0f * dz0, 0.0f);
        float d2z1 = fmaxf(sRzI[i1] + rzj - 2.0f * dz1, 0.0f);
        float aint0 = __expf(-d2z0 * inv2tau);
        float aint1 = __expf(-d2z1 * inv2tau);

        float dp0 = sPiX[i0] * pjx + sPiY[i0] * pjy + sPiZ[i0] * pjz;
        float dp1 = sPiX[i1] * pjx + sPiY[i1] * pjy + sPiZ[i1] * pjz;
        float d2p0 = fmaxf(sRpI[i0] + rpj - 2.0f * dp0, 0.0f);
        float d2p1 = fmaxf(sRpI[i1] + rpj - 2.0f * dp1, 0.0f);
        float asp0 = __expf(-d2p0 * inv2sig);
        float asp1 = __expf(-d2p1 * inv2sig);

        float A0 = w0 * asp0 + w1 * aint0 + w2 * abnd0 + w3;
        float A1 = w0 * asp1 + w1 * aint1 + w2 * abnd1 + w3;
        A0 = __saturatef(A0);
        A1 = __saturatef(A1);
        if (I + i0 == gj) A0 = 0.0f;
        if (I + i1 == gj) A1 = 0.0f;
        sTile[i0][jl] = A0;
        sTile[i1][jl] = A1;
    }
    __syncthreads();

    // write normal orientation: rows I+r, cols J..J+63
    {
        float* baseN = g_A + ((size_t)b * Ndim + I) * Ndim + J;
#pragma unroll
        for (int q = 0; q < 4; q++) {
            int idx = q * 256 + tid;          // float4 slot 0..1023
            int r = idx >> 4;
            int c = (idx & 15) * 4;
            float4 v = make_float4(sTile[r][c], sTile[r][c + 1],
                                   sTile[r][c + 2], sTile[r][c + 3]);
            *(float4*)(baseN + (size_t)r * Ndim + c) = v;
        }
    }
    // transposed orientation: rows J+r, cols I..I+63
    if (ti != tj) {
        float* baseT = g_A + ((size_t)b * Ndim + J) * Ndim + I;
#pragma unroll
        for (int q = 0; q < 4; q++) {
            int idx = q * 256 + tid;
            int r = idx >> 4;
            int c = (idx & 15) * 4;
            float4 v = make_float4(sTile[c][r], sTile[c + 1][r],
                                   sTile[c + 2][r], sTile[c + 3][r]);
            *(float4*)(baseT + (size_t)r * Ndim + c) = v;
        }
    }
}

// ---------------- kernel 4: per-row top-k + normalize -----------------------
// Threshold via 4-round byte histogram descent; histogram fills use
// __match_any_sync aggregation (A values cluster into few exponent bins ->
// plain atomics serialize warp-wide).
__global__ __launch_bounds__(256) void topk_kernel(float* __restrict__ out) {
    __shared__ int sHist[256];
    __shared__ int sCum[256];
    __shared__ int sSel[2];            // selected bin, new strict-greater G
    __shared__ int sWeq[8];
    __shared__ float sWsum[8];

    const int tid = threadIdx.x;
    const int lane = tid & 31;
    const int warp = tid >> 5;
    const int row = blockIdx.x;

    unsigned vb[8];
    {
        const float4* rowp = (const float4*)(g_A + (size_t)row * Ndim);
        float4 a = rowp[tid * 2 + 0];
        float4 c = rowp[tid * 2 + 1];
        vb[0] = __float_as_uint(a.x); vb[1] = __float_as_uint(a.y);
        vb[2] = __float_as_uint(a.z); vb[3] = __float_as_uint(a.w);
        vb[4] = __float_as_uint(c.x); vb[5] = __float_as_uint(c.y);
        vb[6] = __float_as_uint(c.z); vb[7] = __float_as_uint(c.w);
    }

    unsigned P = 0u;   // threshold prefix under construction
    int G = 0;         // strict-greater count from completed rounds

    const int shifts[4]     = {23, 15, 7, 0};
    const int passShifts[4] = {31, 23, 15, 7};

#pragma unroll 1
    for (int rnd = 0; rnd < 4; rnd++) {
        const int shift = shifts[rnd];
        const int pshift = passShifts[rnd];
        const unsigned ppref = P >> pshift;

        sHist[tid] = 0;
        __syncthreads();

#pragma unroll
        for (int r = 0; r < 8; r++) {
            unsigned u = vb[r];
            bool ok = ((u >> pshift) == ppref);
            unsigned bin = ok ? ((u >> shift) & 0xFFu) : 0xFFFFFFFFu;
            unsigned mk = __match_any_sync(0xffffffffu, bin);
            int leader = __ffs(mk) - 1;
            if (ok && lane == leader) atomicAdd(&sHist[bin], __popc(mk));
        }
        __syncthreads();

        // warp 0: suffix scan -> cumGE[b] = count of passing values with bin >= b
        if (warp == 0) {
            int s = 0;
#pragma unroll
            for (int q = 0; q < 8; q++) s += sHist[lane * 8 + q];
            int S = s;  // inclusive suffix sum across lanes
#pragma unroll
            for (int off = 1; off < 32; off <<= 1) {
                int v = __shfl_down_sync(0xffffffffu, S, off);
                if (lane + off < 32) S += v;
            }
            int running = S - s;  // count in lanes above
#pragma unroll
            for (int q = 7; q >= 0; q--) {
                int bidx = lane * 8 + q;
                running += sHist[bidx];
                sCum[bidx] = running;
            }
        }
        __syncthreads();

        // select largest bin b with G + cumGE[b] >= KSEL (cumGE monotone dec.)
        {
            bool c0 = (G + sCum[tid] >= KSEL);
            bool c1 = (tid == 255) ? false : (G + sCum[tid + 1] >= KSEL);
            if (c0 && !c1) {
                sSel[0] = tid;
                sSel[1] = G + sCum[tid] - sHist[tid];
            }
        }
        __syncthreads();
        P |= ((unsigned)sSel[0]) << shift;
        G = sSel[1];
    }

    const unsigned T = P;          // exact K-th largest value bits
    const int need = KSEL - G;     // ties at T to keep, in index order

    // exclusive scan of per-thread equal-to-T counts (global index order)
    int eqc = 0;
#pragma unroll
    for (int r = 0; r < 8; r++) eqc += (vb[r] == T);
    int incl = eqc;
#pragma unroll
    for (int off = 1; off < 32; off <<= 1) {
        int t2 = __shfl_up_sync(0xffffffffu, incl, off);
        if (lane >= off) incl += t2;
    }
    if (lane == 31) sWeq[warp] = incl;
    __syncthreads();
    int ebase = incl - eqc;
    for (int w = 0; w < warp; w++) ebase += sWeq[w];

    float ksum = 0.0f;
    {
        int rk = ebase;
#pragma unroll
        for (int r = 0; r < 8; r++) {
            unsigned u = vb[r];
            float v = __uint_as_float(u);
            if (u > T) ksum += v;
            else if (u == T) { if (rk < need) ksum += v; rk++; }
        }
    }
#pragma unroll
    for (int off = 16; off > 0; off >>= 1)
        ksum += __shfl_xor_sync(0xffffffffu, ksum, off);
    if (lane == 0) sWsum[warp] = ksum;
    __syncthreads();
    float tot = 0.0f;
#pragma unroll
    for (int w = 0; w < 8; w++) tot += sWsum[w];
    const float inv = __fdividef(1.0f, fmaxf(tot, EPSV));

    float ov[8];
    {
        int rk = ebase;
#pragma unroll
        for (int r = 0; r < 8; r++) {
            unsigned u = vb[r];
            float v = __uint_as_float(u);
            bool keep = (u > T);
            if (u == T) { keep = (rk < need); rk++; }
            ov[r] = keep ? v * inv : 0.0f;
        }
    }
    float4* orow4 = (float4*)(out + (size_t)row * Ndim);
    orow4[tid * 2 + 0] = make_float4(ov[0], ov[1], ov[2], ov[3]);
    orow4[tid * 2 + 1] = make_float4(ov[4], ov[5], ov[6], ov[7]);
}

extern "C" void kernel_launch(void* const* d_in, const int* in_sizes, int n_in,
                              void* d_out, int out_size) {
    const float* features     = (const float*)d_in[0];
    const float* positions    = (const float*)d_in[1];
    const float* Wi1          = (const float*)d_in[2];
    const float* bi1          = (const float*)d_in[3];
    const float* Wi2          = (const float*)d_in[4];
    const float* bi2          = (const float*)d_in[5];
    const float* Wb1          = (const float*)d_in[6];
    const float* bb1          = (const float*)d_in[7];
    const float* Wb2          = (const float*)d_in[8];
    const float* bb2          = (const float*)d_in[9];
    const float* log_sigma    = (const float*)d_in[10];
    const float* log_tau      = (const float*)d_in[11];
    const float* log_alpha    = (const float*)d_in[12];
    // d_in[13] = log_gamma (unused: EMA buffer empty -> stability == 1)
    const float* prior_logits = (const float*)d_in[14];
    float* out = (float*)d_out;

    prep_kernel<<<(Ndim + 255) / 256, 256>>>(positions);
    z_kernel<<<(Bdim * Ndim * 32) / 256, 256>>>(features, Wi1, bi1, Wi2, bi2);
    tile_kernel<<<Bdim * NTRI, 256>>>(positions, Wb1, bb1, Wb2, bb2,
                                      log_sigma, log_tau, log_alpha, prior_logits);
    topk_kernel<<<Bdim * Ndim, 256>>>(out);
}

// round 7
// speedup vs baseline: 1.3282x; 1.3282x over previous
#include <cuda_runtime.h>
#include <math.h>

#define Bdim 2
#define Ndim 2048
#define Edim 384
#define DPdim 16
#define KSEL 32
#define EPSV 1e-8f
#define TN 64
#define NT (Ndim / TN)            // 32
#define NTRI (NT * (NT + 1) / 2)  // 528
#define NTILES (Bdim * NTRI)      // 1056
#define PERSIST_CTAS 296

// scratch (device globals: no allocation allowed)
__device__ float g_z[Bdim * Ndim * DPdim];
__device__ float g_rz[Bdim * Ndim];
__device__ float g_rp[Ndim];
__device__ float g_A[(size_t)Bdim * Ndim * Ndim];  // 33.5 MB dense prior matrix
__device__ int g_ticket;

// Abramowitz-Stegun 7.1.26, max abs err 1.5e-7, branch-free
__device__ __forceinline__ float erf_fast(float x) {
    float ax = fabsf(x);
    float t = __fdividef(1.0f, fmaf(0.3275911f, ax, 1.0f));
    float poly = t * fmaf(t, fmaf(t, fmaf(t, fmaf(t, 1.061405429f, -1.453152027f),
                                          1.421413741f), -0.284496736f), 0.254829592f);
    float r = 1.0f - poly * __expf(-ax * ax);
    return copysignf(r, x);
}

__device__ __forceinline__ float gelu_exact(float x) {
    return 0.5f * x * (1.0f + erf_fast(x * 0.70710678118654752f));
}

// ---------------- kernel 1: rp[n] = ||positions[n]||^2; reset ticket --------
__global__ void prep_kernel(const float* __restrict__ positions) {
    int n = blockIdx.x * blockDim.x + threadIdx.x;
    if (n == 0) g_ticket = 0;
    if (n < Ndim) {
        float x = positions[3 * n + 0];
        float y = positions[3 * n + 1];
        float z = positions[3 * n + 2];
        g_rp[n] = x * x + y * y + z * z;
    }
}

// ---------------- kernel 2: z = gelu(f@Wi1+bi1)@Wi2+bi2, rz = ||z||^2 ----
__global__ __launch_bounds__(256) void z_kernel(
    const float* __restrict__ feat, const float* __restrict__ Wi1,
    const float* __restrict__ bi1, const float* __restrict__ Wi2,
    const float* __restrict__ bi2)
{
    int gwarp = (blockIdx.x * blockDim.x + threadIdx.x) >> 5;
    int lane = threadIdx.x & 31;
    if (gwarp >= Bdim * Ndim) return;

    const float* x = feat + (size_t)gwarp * Edim;
    float acc = 0.0f;
    for (int e0 = 0; e0 < Edim; e0 += 32) {
        float xv = x[e0 + lane];
#pragma unroll
        for (int i = 0; i < 32; i++) {
            float xb = __shfl_sync(0xffffffffu, xv, i);
            acc = fmaf(xb, Wi1[(e0 + i) * 32 + lane], acc);
        }
    }
    float hg = gelu_exact(acc + bi1[lane]);

    float wv[DPdim];
#pragma unroll
    for (int d = 0; d < DPdim; d++) wv[d] = Wi2[lane * DPdim + d];

    float zv = 0.0f;
#pragma unroll
    for (int d = 0; d < DPdim; d++) {
        float p = hg * wv[d];
#pragma unroll
        for (int off = 16; off > 0; off >>= 1)
            p += __shfl_xor_sync(0xffffffffu, p, off);
        if (lane == d) zv = p + bi2[d];
    }
    if (lane < DPdim) g_z[gwarp * DPdim + lane] = zv;

    float q = (lane < DPdim) ? zv * zv : 0.0f;
#pragma unroll
    for (int off = 16; off > 0; off >>= 1)
        q += __shfl_xor_sync(0xffffffffu, q, off);
    if (lane == 0) g_rz[gwarp] = q;
}

// ---------------- kernel 3: persistent triangular tile pair-compute ---------
// PERSIST_CTAS persistent blocks pull 64x64 tiles (ti <= tj) off a global
// ticket. Each tile written in both orientations (A symmetric by construction).
// Fixed column j per thread, 4 i-rows per inner iteration.
__global__ __launch_bounds__(256) void tile_kernel(
    const float* __restrict__ positions,
    const float* __restrict__ Wb1, const float* __restrict__ bb1,
    const float* __restrict__ Wb2, const float* __restrict__ bb2,
    const float* __restrict__ p_sig, const float* __restrict__ p_tau,
    const float* __restrict__ p_alp, const float* __restrict__ prior_logits)
{
    __shared__ float sZi[TN * DPdim];
    __shared__ float sRzI[TN], sRpI[TN];
    __shared__ float sPiX[TN], sPiY[TN], sPiZ[TN];
    __shared__ float4 sWb1v[DPdim * DPdim / 4];
    __shared__ float sWb2[DPdim];
    __shared__ float sBb1[DPdim];
    __shared__ float sScal[8]; // inv2sig, inv2tau, alpha, w0..w3, bb2
    __shared__ float sTile[TN][TN + 1];
    __shared__ int sTicket;

    const int tid = threadIdx.x;
    const int jl = tid & 63;
    const int ig = tid >> 6;   // 0..3: i-band of 16 rows

    // once-per-CTA loads (weights + scalars)
    if (tid < 64) sWb1v[tid] = ((const float4*)Wb1)[tid];
    if (tid >= 64 && tid < 80) {
        sWb2[tid - 64] = Wb2[tid - 64];
        sBb1[tid - 64] = bb1[tid - 64];
    }
    if (tid == 128) {
        float sg = log1pf(__expf(p_sig[0]));
        float ta = log1pf(__expf(p_tau[0]));
        float al = log1pf(__expf(p_alp[0]));
        sScal[0] = __fdividef(1.0f, 2.0f * sg * sg + EPSV);
        sScal[1] = __fdividef(1.0f, 2.0f * ta * ta + EPSV);
        sScal[2] = al;
        float l0 = prior_logits[0], l1 = prior_logits[1];
        float l2 = prior_logits[2], l3 = prior_logits[3];
        float m = fmaxf(fmaxf(l0, l1), fmaxf(l2, l3));
        float e0 = __expf(l0 - m), e1 = __expf(l1 - m);
        float e2 = __expf(l2 - m), e3 = __expf(l3 - m);
        float inv = __fdividef(1.0f, e0 + e1 + e2 + e3);
        sScal[3] = e0 * inv; sScal[4] = e1 * inv;
        sScal[5] = e2 * inv; sScal[6] = e3 * inv;
        sScal[7] = bb2[0];
    }
    __syncthreads();

    const float inv2sig = sScal[0], inv2tau = sScal[1], alpha = sScal[2];
    const float w0 = sScal[3], w1 = sScal[4], w2 = sScal[5], w3 = sScal[6];
    const float bb2v = sScal[7];

    for (;;) {
        if (tid == 0) sTicket = atomicAdd(&g_ticket, 1);
        __syncthreads();
        const int tk = sTicket;
        if (tk >= NTILES) break;

        // decode (b, ti, tj)
        const int b = tk / NTRI;
        int tri = tk - b * NTRI;
        int ti = 0;
        while (tri >= NT - ti) { tri -= NT - ti; ti++; }
        const int tj = ti + tri;
        const int I = ti * TN, J = tj * TN;

        // per-tile i-side loads
        {   // sZi: 64 rows x 16 floats = 256 float4
            const float4* zgi = (const float4*)(g_z + ((size_t)b * Ndim + I) * DPdim);
            ((float4*)sZi)[tid] = zgi[tid];
        }
        if (tid < 64) {
            int gi = I + tid;
            sRzI[tid] = g_rz[(size_t)b * Ndim + gi];
            sRpI[tid] = g_rp[gi];
            sPiX[tid] = positions[3 * gi + 0];
            sPiY[tid] = positions[3 * gi + 1];
            sPiZ[tid] = positions[3 * gi + 2];
        }

        // per-thread j-side data (fixed column)
        const int gj = J + jl;
        float zj[DPdim];
        {
            const float4* zgj = (const float4*)(g_z + ((size_t)b * Ndim + gj) * DPdim);
            float4* v = (float4*)zj;
#pragma unroll
            for (int q = 0; q < 4; q++) v[q] = zgj[q];
        }
        const float rzj = g_rz[(size_t)b * Ndim + gj];
        const float rpj = g_rp[gj];
        const float pjx = positions[3 * gj + 0];
        const float pjy = positions[3 * gj + 1];
        const float pjz = positions[3 * gj + 2];

        __syncthreads();

        // 4 iterations x 4 i-rows per thread
#pragma unroll 1
        for (int it = 0; it < 4; it++) {
            const int ib = ig * 16 + it * 4;

            float h[4][DPdim];
#pragma unroll
            for (int r = 0; r < 4; r++)
#pragma unroll
                for (int o = 0; o < DPdim; o++) h[r][o] = sBb1[o];

            float dz[4] = {0.0f, 0.0f, 0.0f, 0.0f};
#pragma unroll
            for (int d = 0; d < DPdim; d++) {
                float zjd = zj[d];
                float e[4];
#pragma unroll
                for (int r = 0; r < 4; r++) {
                    float zir = sZi[(ib + r) * DPdim + d];
                    dz[r] = fmaf(zir, zjd, dz[r]);
                    e[r] = fabsf(zir - zjd);
                }
#pragma unroll
                for (int o4 = 0; o4 < 4; o4++) {
                    float4 w = sWb1v[d * 4 + o4];
#pragma unroll
                    for (int r = 0; r < 4; r++) {
                        h[r][o4 * 4 + 0] = fmaf(e[r], w.x, h[r][o4 * 4 + 0]);
                        h[r][o4 * 4 + 1] = fmaf(e[r], w.y, h[r][o4 * 4 + 1]);
                        h[r][o4 * 4 + 2] = fmaf(e[r], w.z, h[r][o4 * 4 + 2]);
                        h[r][o4 * 4 + 3] = fmaf(e[r], w.w, h[r][o4 * 4 + 3]);
                    }
                }
            }

#pragma unroll
            for (int r = 0; r < 4; r++) {
                const int ii = ib + r;
                float s = bb2v;
#pragma unroll
                for (int o = 0; o < DPdim; o++)
                    s = fmaf(gelu_exact(h[r][o]), sWb2[o], s);
                float abnd = __fdividef(1.0f, 1.0f + __expf(alpha * s));

                float d2z = fmaxf(sRzI[ii] + rzj - 2.0f * dz[r], 0.0f);
                float aint = __expf(-d2z * inv2tau);

                float dp = sPiX[ii] * pjx + sPiY[ii] * pjy + sPiZ[ii] * pjz;
                float d2p = fmaxf(sRpI[ii] + rpj - 2.0f * dp, 0.0f);
                float asp = __expf(-d2p * inv2sig);

                float A = w0 * asp + w1 * aint + w2 * abnd + w3;
                A = __saturatef(A);
                if (I + ii == gj) A = 0.0f;
                sTile[ii][jl] = A;
            }
        }
        __syncthreads();

        // write normal orientation: rows I+r, cols J..J+63
        {
            float* baseN = g_A + ((size_t)b * Ndim + I) * Ndim + J;
#pragma unroll
            for (int q = 0; q < 4; q++) {
                int idx = q * 256 + tid;          // float4 slot 0..1023
                int r = idx >> 4;
                int c = (idx & 15) * 4;
                float4 v = make_float4(sTile[r][c], sTile[r][c + 1],
                                       sTile[r][c + 2], sTile[r][c + 3]);
                *(float4*)(baseN + (size_t)r * Ndim + c) = v;
            }
        }
        // transposed orientation: rows J+r, cols I..I+63
        if (ti != tj) {
            float* baseT = g_A + ((size_t)b * Ndim + J) * Ndim + I;
#pragma unroll
            for (int q = 0; q < 4; q++) {
                int idx = q * 256 + tid;
                int r = idx >> 4;
                int c = (idx & 15) * 4;
                float4 v = make_float4(sTile[c][r], sTile[c + 1][r],
                                       sTile[c + 2][r], sTile[c + 3][r]);
                *(float4*)(baseT + (size_t)r * Ndim + c) = v;
            }
        }
        __syncthreads();  // protect sZi/sTile before next tile overwrites
    }
}

// ---------------- kernel 4: per-row top-k + normalize -----------------------
// Threshold via 4-round byte histogram descent (exact, jax tie semantics).
__global__ __launch_bounds__(256) void topk_kernel(float* __restrict__ out) {
    __shared__ int sHist[8][256];      // per-warp histograms
    __shared__ int sTot[256];
    __shared__ int sCum[256];          // cumGE per bin
    __shared__ int sSel[2];            // selected bin, new strict-greater G
    __shared__ int sWeq[8];
    __shared__ float sWsum[8];

    const int tid = threadIdx.x;
    const int lane = tid & 31;
    const int warp = tid >> 5;
    const int row = blockIdx.x;

    unsigned vb[8];
    {
        const float4* rowp = (const float4*)(g_A + (size_t)row * Ndim);
        float4 a = rowp[tid * 2 + 0];
        float4 c = rowp[tid * 2 + 1];
        vb[0] = __float_as_uint(a.x); vb[1] = __float_as_uint(a.y);
        vb[2] = __float_as_uint(a.z); vb[3] = __float_as_uint(a.w);
        vb[4] = __float_as_uint(c.x); vb[5] = __float_as_uint(c.y);
        vb[6] = __float_as_uint(c.z); vb[7] = __float_as_uint(c.w);
    }

    unsigned P = 0u;   // threshold prefix under construction
    int G = 0;         // strict-greater count from completed rounds

    const int shifts[4]     = {23, 15, 7, 0};
    const int passShifts[4] = {31, 23, 15, 7};

#pragma unroll 1
    for (int rnd = 0; rnd < 4; rnd++) {
        const int shift = shifts[rnd];
        const int pshift = passShifts[rnd];
        const unsigned ppref = P >> pshift;

        // clear per-warp histograms (8*256 ints, 8 per thread)
#pragma unroll
        for (int q = 0; q < 8; q++) ((int*)sHist)[q * 256 + tid] = 0;
        __syncthreads();

#pragma unroll
        for (int r = 0; r < 8; r++) {
            unsigned u = vb[r];
            if ((u >> pshift) == ppref)
                atomicAdd(&sHist[warp][(u >> shift) & 0xFF], 1);
        }
        __syncthreads();

        // totals per bin
        int t = 0;
#pragma unroll
        for (int w = 0; w < 8; w++) t += sHist[w][tid];
        sTot[tid] = t;
        __syncthreads();

        // warp 0: suffix scan -> cumGE[b] = count of passing values with bin >= b
        if (warp == 0) {
            int s = 0;
#pragma unroll
            for (int q = 0; q < 8; q++) s += sTot[lane * 8 + q];
            int S = s;  // inclusive suffix sum across lanes
#pragma unroll
            for (int off = 1; off < 32; off <<= 1) {
                int v = __shfl_down_sync(0xffffffffu, S, off);
                if (lane + off < 32) S += v;
            }
            int running = S - s;  // count in lanes above
#pragma unroll
            for (int q = 7; q >= 0; q--) {
                int bidx = lane * 8 + q;
                running += sTot[bidx];
                sCum[bidx] = running;
            }
        }
        __syncthreads();

        // select largest bin b with G + cumGE[b] >= KSEL (cumGE monotone dec.)
        {
            bool c0 = (G + sCum[tid] >= KSEL);
            bool c1 = (tid == 255) ? false : (G + sCum[tid + 1] >= KSEL);
            if (c0 && !c1) {
                sSel[0] = tid;
                sSel[1] = G + sCum[tid] - sTot[tid];
            }
        }
        __syncthreads();
        P |= ((unsigned)sSel[0]) << shift;
        G = sSel[1];
        __syncthreads();
    }

    const unsigned T = P;          // exact K-th largest value bits
    const int need = KSEL - G;     // ties at T to keep, in index order

    // exclusive scan of per-thread equal-to-T counts (global index order)
    int eqc = 0;
#pragma unroll
    for (int r = 0; r < 8; r++) eqc += (vb[r] == T);
    int incl = eqc;
#pragma unroll
    for (int off = 1; off < 32; off <<= 1) {
        int t2 = __shfl_up_sync(0xffffffffu, incl, off);
        if (lane >= off) incl += t2;
    }
    if (lane == 31) sWeq[warp] = incl;
    __syncthreads();
    int ebase = incl - eqc;
    for (int w = 0; w < warp; w++) ebase += sWeq[w];

    float ksum = 0.0f;
    {
        int rk = ebase;
#pragma unroll
        for (int r = 0; r < 8; r++) {
            unsigned u = vb[r];
            float v = __uint_as_float(u);
            if (u > T) ksum += v;
            else if (u == T) { if (rk < need) ksum += v; rk++; }
        }
    }
#pragma unroll
    for (int off = 16; off > 0; off >>= 1)
        ksum += __shfl_xor_sync(0xffffffffu, ksum, off);
    if (lane == 0) sWsum[warp] = ksum;
    __syncthreads();
    float tot = 0.0f;
#pragma unroll
    for (int w = 0; w < 8; w++) tot += sWsum[w];
    const float inv = __fdividef(1.0f, fmaxf(tot, EPSV));

    float ov[8];
    {
        int rk = ebase;
#pragma unroll
        for (int r = 0; r < 8; r++) {
            unsigned u = vb[r];
            float v = __uint_as_float(u);
            bool keep = (u > T);
            if (u == T) { keep = (rk < need); rk++; }
            ov[r] = keep ? v * inv : 0.0f;
        }
    }
    float4* orow4 = (float4*)(out + (size_t)row * Ndim);
    orow4[tid * 2 + 0] = make_float4(ov[0], ov[1], ov[2], ov[3]);
    orow4[tid * 2 + 1] = make_float4(ov[4], ov[5], ov[6], ov[7]);
}

extern "C" void kernel_launch(void* const* d_in, const int* in_sizes, int n_in,
                              void* d_out, int out_size) {
    const float* features     = (const float*)d_in[0];
    const float* positions    = (const float*)d_in[1];
    const float* Wi1          = (const float*)d_in[2];
    const float* bi1          = (const float*)d_in[3];
    const float* Wi2          = (const float*)d_in[4];
    const float* bi2          = (const float*)d_in[5];
    const float* Wb1          = (const float*)d_in[6];
    const float* bb1          = (const float*)d_in[7];
    const float* Wb2          = (const float*)d_in[8];
    const float* bb2          = (const float*)d_in[9];
    const float* log_sigma    = (const float*)d_in[10];
    const float* log_tau      = (const float*)d_in[11];
    const float* log_alpha    = (const float*)d_in[12];
    // d_in[13] = log_gamma (unused: EMA buffer empty -> stability == 1)
    const float* prior_logits = (const float*)d_in[14];
    float* out = (float*)d_out;

    prep_kernel<<<(Ndim + 255) / 256, 256>>>(positions);
    z_kernel<<<(Bdim * Ndim * 32) / 256, 256>>>(features, Wi1, bi1, Wi2, bi2);
    tile_kernel<<<PERSIST_CTAS, 256>>>(positions, Wb1, bb1, Wb2, bb2,
                                       log_sigma, log_tau, log_alpha, prior_logits);
    topk_kernel<<<Bdim * Ndim, 256>>>(out);
}